// round 3
// baseline (speedup 1.0000x reference)
#include <cuda_runtime.h>
#include <cuda_bf16.h>

// ---------------------------------------------------------------------------
// Block-sparse attention prefill (HSA): per-(l,h,g,s) independent unit:
//   scores = q . K_blk * sm_scale  (64 keys x 128 dim)
//   p = softmax_64(scores) * w[l,hq,s] * (blk >= 0)
//   o += p . V_blk
// Shapes: B=1, Lq=256, Lkv=4096, HQ=32, H=2, D=128, S=16, BS=64, G=16
// ---------------------------------------------------------------------------

#define FMA2(acc, a, b) asm("fma.rn.f32x2 %0, %1, %2, %0;" : "+l"(acc) : "l"(a), "l"(b))

__device__ __forceinline__ unsigned long long pack2(float lo, float hi) {
    unsigned long long r;
    asm("mov.b64 %0, {%1, %2};" : "=l"(r) : "f"(lo), "f"(hi));
    return r;
}
__device__ __forceinline__ void unpack2(unsigned long long v, float& lo, float& hi) {
    asm("mov.b64 {%0, %1}, %2;" : "=f"(lo), "=f"(hi) : "l"(v));
}

namespace hsa {
constexpr int LQ = 256;
constexpr int HQn = 32;
constexpr int Hn = 2;
constexpr int Dn = 128;
constexpr int Sn = 16;
constexpr int BSn = 64;
constexpr int Gn = 16;
constexpr int KROW = 132;   // padded smem row stride in floats (16B-aligned rows,
                            // 4-phase-optimal LDS.128 column reads)
constexpr float SM_SCALE = 0.08838834764831845f;  // 1/sqrt(128)

// smem layout (in floats)
constexpr int SM_K = 0;
constexpr int SM_V = SM_K + BSn * KROW;      // 8448
constexpr int SM_Q = SM_V + BSn * KROW;      // 16896
constexpr int SM_P = SM_Q + Gn * Dn;         // + 2048 -> 18944
constexpr int SM_W = SM_P + 4 * BSn * 8;     // 4 warps * 64 * 8 -> 20992
constexpr int SM_I = SM_W + Gn * Sn;         // + 256 -> 21248
constexpr int SMEM_FLOATS = SM_I + 16;       // 16 ints aliased at tail
constexpr int SMEM_BYTES = SMEM_FLOATS * 4;  // 85056 B -> 2 CTAs/SM
}  // namespace hsa

using namespace hsa;

__global__ __launch_bounds__(128, 2)
void hsa_prefill_kernel(const float* __restrict__ q, const float* __restrict__ k,
                        const float* __restrict__ v, const float* __restrict__ w,
                        const int* __restrict__ bi, float* __restrict__ out)
{
    extern __shared__ float sm[];
    float* ks  = sm + SM_K;
    float* vs  = sm + SM_V;
    float* qs  = sm + SM_Q;
    float* ps  = sm + SM_P;
    float* wsm = sm + SM_W;
    int*   bis = (int*)(sm + SM_I);

    const int h    = blockIdx.x;   // kv head (0..1)
    const int l    = blockIdx.y;   // query position (0..255)
    const int tid  = threadIdx.x;
    const int warp = tid >> 5;
    const int lane = tid & 31;

    // --- Stage q (pre-scaled), w, block indices into smem ---
    {
        // q[l, h*G + g, d]: 16 heads x 128 d contiguous (2048 floats)
        const float4* qg = (const float4*)(q + (size_t)(l * HQn + h * Gn) * Dn);
        float4* qs4 = (float4*)qs;
        #pragma unroll
        for (int j = 0; j < 4; ++j) {
            int i = tid + j * 128;
            float4 t = qg[i];
            t.x *= SM_SCALE; t.y *= SM_SCALE; t.z *= SM_SCALE; t.w *= SM_SCALE;
            qs4[i] = t;
        }
        if (tid < 64)
            ((float4*)wsm)[tid] =
                ((const float4*)(w + (size_t)(l * HQn + h * Gn) * Sn))[tid];
        if (tid < 16)
            bis[tid] = bi[(l * Hn + h) * Sn + tid];
    }
    __syncthreads();

    const int g0 = warp * 4;              // each warp owns 4 query heads
    unsigned long long o[4][2];           // o[g][dpair] : f32x2 over (4*lane+{0,1},{2,3})
    #pragma unroll
    for (int a = 0; a < 4; ++a) { o[a][0] = 0ull; o[a][1] = 0ull; }

    const float4* kb = (const float4*)(k + h * Dn);  // k[key,h,d] row stride 256 fl = 64 f4
    const float4* vb = (const float4*)(v + h * Dn);
    float* psw = ps + warp * (BSn * 8);

    for (int s = 0; s < Sn; ++s) {
        const int blk = bis[s];           // uniform across CTA
        if (blk < 0) continue;

        __syncthreads();                  // protect smem K/V/p from previous iter's readers
        // --- Gather K/V block (64 x 128 f32 each) into padded smem ---
        {
            const float4* krow = kb + (size_t)blk * BSn * (Hn * Dn / 4);
            const float4* vrow = vb + (size_t)blk * BSn * (Hn * Dn / 4);
            #pragma unroll
            for (int j = 0; j < 16; ++j) {
                int c = tid + j * 128;
                int u = c >> 5, d4 = c & 31;              // warp = one full 512B row
                int gidx = u * (Hn * Dn / 4) + d4;
                int sidx = u * KROW + d4 * 4;
                *(float4*)(ks + sidx) = krow[gidx];
                *(float4*)(vs + sidx) = vrow[gidx];
            }
        }
        __syncthreads();

        // --- QK: lanes over u (u = lane, lane+32), f32x2 packed over d pairs ---
        unsigned long long acc[4][2];
        #pragma unroll
        for (int a = 0; a < 4; ++a) { acc[a][0] = 0ull; acc[a][1] = 0ull; }
        const ulonglong2* k0p = (const ulonglong2*)(ks + lane * KROW);
        const ulonglong2* k1p = (const ulonglong2*)(ks + (lane + 32) * KROW);
        #pragma unroll 8
        for (int dd = 0; dd < 32; ++dd) {
            ulonglong2 ka = k0p[dd];      // k[lane   ][4dd..4dd+3]
            ulonglong2 kc = k1p[dd];      // k[lane+32][4dd..4dd+3]
            #pragma unroll
            for (int gj = 0; gj < 4; ++gj) {
                ulonglong2 qv = *(const ulonglong2*)(qs + (g0 + gj) * Dn + dd * 4);
                FMA2(acc[gj][0], qv.x, ka.x);
                FMA2(acc[gj][0], qv.y, ka.y);
                FMA2(acc[gj][1], qv.x, kc.x);
                FMA2(acc[gj][1], qv.y, kc.y);
            }
        }

        // --- per-block softmax over 64 keys + weight; store p duplicated {p,p} ---
        #pragma unroll
        for (int gj = 0; gj < 4; ++gj) {
            float a0, a1, b0, b1;
            unpack2(acc[gj][0], a0, a1);
            unpack2(acc[gj][1], b0, b1);
            float s0 = a0 + a1;           // score(u=lane)
            float s1 = b0 + b1;           // score(u=lane+32)
            float m = fmaxf(s0, s1);
            #pragma unroll
            for (int off = 16; off > 0; off >>= 1)
                m = fmaxf(m, __shfl_xor_sync(0xffffffffu, m, off));
            float e0 = __expf(s0 - m);
            float e1 = __expf(s1 - m);
            float sum = e0 + e1;
            #pragma unroll
            for (int off = 16; off > 0; off >>= 1)
                sum += __shfl_xor_sync(0xffffffffu, sum, off);
            float coef = wsm[(g0 + gj) * Sn + s] / sum;
            e0 *= coef; e1 *= coef;
            *(unsigned long long*)(psw + lane * 8 + gj * 2)        = pack2(e0, e0);
            *(unsigned long long*)(psw + (lane + 32) * 8 + gj * 2) = pack2(e1, e1);
        }
        __syncwarp();

        // --- PV: lanes over d (4 per lane); p read pre-duplicated -> no packs ---
        #pragma unroll 8
        for (int u = 0; u < BSn; ++u) {
            ulonglong2 pa = *(const ulonglong2*)(psw + u * 8);       // {p0,p0},{p1,p1}
            ulonglong2 pb = *(const ulonglong2*)(psw + u * 8 + 4);   // {p2,p2},{p3,p3}
            ulonglong2 vv = *(const ulonglong2*)(vs + u * KROW + lane * 4);
            FMA2(o[0][0], pa.x, vv.x); FMA2(o[0][1], pa.x, vv.y);
            FMA2(o[1][0], pa.y, vv.x); FMA2(o[1][1], pa.y, vv.y);
            FMA2(o[2][0], pb.x, vv.x); FMA2(o[2][1], pb.x, vv.y);
            FMA2(o[3][0], pb.y, vv.x); FMA2(o[3][1], pb.y, vv.y);
        }
    }

    // --- write O: out[l, h*G + g, 4*lane .. +3] ---
    float* op = out + (size_t)(l * HQn + h * Gn) * Dn;
    #pragma unroll
    for (int gj = 0; gj < 4; ++gj) {
        float f0, f1, f2, f3;
        unpack2(o[gj][0], f0, f1);
        unpack2(o[gj][1], f2, f3);
        float4 r = make_float4(f0, f1, f2, f3);
        *(float4*)(op + (g0 + gj) * Dn + lane * 4) = r;
    }
}

extern "C" void kernel_launch(void* const* d_in, const int* in_sizes, int n_in,
                              void* d_out, int out_size) {
    const float* q  = (const float*)d_in[0];
    const float* k  = (const float*)d_in[1];
    const float* v  = (const float*)d_in[2];
    const float* w  = (const float*)d_in[3];
    const int*   bi = (const int*)d_in[4];
    float* out = (float*)d_out;

    cudaFuncSetAttribute(hsa_prefill_kernel,
                         cudaFuncAttributeMaxDynamicSharedMemorySize, SMEM_BYTES);
    dim3 grid(Hn, LQ);   // 2 x 256 = 512 CTAs
    hsa_prefill_kernel<<<grid, 128, SMEM_BYTES>>>(q, k, v, w, bi, out);
}

// round 4
// speedup vs baseline: 1.0047x; 1.0047x over previous
#include <cuda_runtime.h>
#include <cuda_bf16.h>

// ---------------------------------------------------------------------------
// Block-sparse attention prefill (HSA): per-(l,h,g,s) independent unit:
//   scores = q . K_blk * sm_scale  (64 keys x 128 dim)
//   p = softmax_64(scores) * w[l,hq,s] * (blk >= 0)
//   o += p . V_blk
// Shapes: B=1, Lq=256, Lkv=4096, HQ=32, H=2, D=128, S=16, BS=64, G=16
// ---------------------------------------------------------------------------

#define FMA2(acc, a, b) asm("fma.rn.f32x2 %0, %1, %2, %0;" : "+l"(acc) : "l"(a), "l"(b))

__device__ __forceinline__ unsigned long long pack2(float lo, float hi) {
    unsigned long long r;
    asm("mov.b64 %0, {%1, %2};" : "=l"(r) : "f"(lo), "f"(hi));
    return r;
}
__device__ __forceinline__ void unpack2(unsigned long long v, float& lo, float& hi) {
    asm("mov.b64 {%0, %1}, %2;" : "=f"(lo), "=f"(hi) : "l"(v));
}

namespace hsa {
constexpr int LQ = 256;
constexpr int HQn = 32;
constexpr int Hn = 2;
constexpr int Dn = 128;
constexpr int Sn = 16;
constexpr int BSn = 64;
constexpr int Gn = 16;
constexpr int KROW = 132;   // padded smem row stride in floats (16B-aligned rows,
                            // 4-phase-optimal LDS.128 column reads)
constexpr float SM_SCALE = 0.08838834764831845f;  // 1/sqrt(128)

// smem layout (in floats)
constexpr int SM_K = 0;
constexpr int SM_V = SM_K + BSn * KROW;      // 8448
constexpr int SM_Q = SM_V + BSn * KROW;      // 16896
constexpr int SM_P = SM_Q + Gn * Dn;         // + 2048 -> 18944
constexpr int SM_W = SM_P + 4 * BSn * 8;     // 4 warps * 64 * 8 -> 20992
constexpr int SM_I = SM_W + Gn * Sn;         // + 256 -> 21248
constexpr int SMEM_FLOATS = SM_I + 16;       // 16 ints aliased at tail
constexpr int SMEM_BYTES = SMEM_FLOATS * 4;  // 85056 B -> 2 CTAs/SM
}  // namespace hsa

using namespace hsa;

__global__ __launch_bounds__(128, 2)
void hsa_prefill_kernel(const float* __restrict__ q, const float* __restrict__ k,
                        const float* __restrict__ v, const float* __restrict__ w,
                        const int* __restrict__ bi, float* __restrict__ out)
{
    extern __shared__ float sm[];
    float* ks  = sm + SM_K;
    float* vs  = sm + SM_V;
    float* qs  = sm + SM_Q;
    float* ps  = sm + SM_P;
    float* wsm = sm + SM_W;
    int*   bis = (int*)(sm + SM_I);

    const int h    = blockIdx.x;   // kv head (0..1)
    const int l    = blockIdx.y;   // query position (0..255)
    const int tid  = threadIdx.x;
    const int warp = tid >> 5;
    const int lane = tid & 31;

    // --- Stage q (pre-scaled), w, block indices into smem ---
    {
        // q[l, h*G + g, d]: 16 heads x 128 d contiguous (2048 floats)
        const float4* qg = (const float4*)(q + (size_t)(l * HQn + h * Gn) * Dn);
        float4* qs4 = (float4*)qs;
        #pragma unroll
        for (int j = 0; j < 4; ++j) {
            int i = tid + j * 128;
            float4 t = qg[i];
            t.x *= SM_SCALE; t.y *= SM_SCALE; t.z *= SM_SCALE; t.w *= SM_SCALE;
            qs4[i] = t;
        }
        if (tid < 64)
            ((float4*)wsm)[tid] =
                ((const float4*)(w + (size_t)(l * HQn + h * Gn) * Sn))[tid];
        if (tid < 16)
            bis[tid] = bi[(l * Hn + h) * Sn + tid];
    }
    __syncthreads();

    const int g0 = warp * 4;              // each warp owns 4 query heads
    unsigned long long o[4][2];           // o[g][dpair] : f32x2 over (4*lane+{0,1},{2,3})
    #pragma unroll
    for (int a = 0; a < 4; ++a) { o[a][0] = 0ull; o[a][1] = 0ull; }

    const float4* kb = (const float4*)(k + h * Dn);  // k[key,h,d] row stride 256 fl = 64 f4
    const float4* vb = (const float4*)(v + h * Dn);
    float* psw = ps + warp * (BSn * 8);

    for (int s = 0; s < Sn; ++s) {
        const int blk = bis[s];           // uniform across CTA
        if (blk < 0) continue;

        __syncthreads();                  // protect smem K/V/p from previous iter's readers
        // --- Gather K/V block (64 x 128 f32 each) into padded smem ---
        {
            const float4* krow = kb + (size_t)blk * BSn * (Hn * Dn / 4);
            const float4* vrow = vb + (size_t)blk * BSn * (Hn * Dn / 4);
            #pragma unroll
            for (int j = 0; j < 16; ++j) {
                int c = tid + j * 128;
                int u = c >> 5, d4 = c & 31;              // warp = one full 512B row
                int gidx = u * (Hn * Dn / 4) + d4;
                int sidx = u * KROW + d4 * 4;
                *(float4*)(ks + sidx) = krow[gidx];
                *(float4*)(vs + sidx) = vrow[gidx];
            }
        }
        __syncthreads();

        // --- QK: lanes over u (u = lane, lane+32), f32x2 packed over d pairs ---
        unsigned long long acc[4][2];
        #pragma unroll
        for (int a = 0; a < 4; ++a) { acc[a][0] = 0ull; acc[a][1] = 0ull; }
        const ulonglong2* k0p = (const ulonglong2*)(ks + lane * KROW);
        const ulonglong2* k1p = (const ulonglong2*)(ks + (lane + 32) * KROW);
        #pragma unroll 8
        for (int dd = 0; dd < 32; ++dd) {
            ulonglong2 ka = k0p[dd];      // k[lane   ][4dd..4dd+3]
            ulonglong2 kc = k1p[dd];      // k[lane+32][4dd..4dd+3]
            #pragma unroll
            for (int gj = 0; gj < 4; ++gj) {
                ulonglong2 qv = *(const ulonglong2*)(qs + (g0 + gj) * Dn + dd * 4);
                FMA2(acc[gj][0], qv.x, ka.x);
                FMA2(acc[gj][0], qv.y, ka.y);
                FMA2(acc[gj][1], qv.x, kc.x);
                FMA2(acc[gj][1], qv.y, kc.y);
            }
        }

        // --- per-block softmax over 64 keys + weight; store p duplicated {p,p} ---
        #pragma unroll
        for (int gj = 0; gj < 4; ++gj) {
            float a0, a1, b0, b1;
            unpack2(acc[gj][0], a0, a1);
            unpack2(acc[gj][1], b0, b1);
            float s0 = a0 + a1;           // score(u=lane)
            float s1 = b0 + b1;           // score(u=lane+32)
            float m = fmaxf(s0, s1);
            #pragma unroll
            for (int off = 16; off > 0; off >>= 1)
                m = fmaxf(m, __shfl_xor_sync(0xffffffffu, m, off));
            float e0 = __expf(s0 - m);
            float e1 = __expf(s1 - m);
            float sum = e0 + e1;
            #pragma unroll
            for (int off = 16; off > 0; off >>= 1)
                sum += __shfl_xor_sync(0xffffffffu, sum, off);
            float coef = wsm[(g0 + gj) * Sn + s] / sum;
            e0 *= coef; e1 *= coef;
            *(unsigned long long*)(psw + lane * 8 + gj * 2)        = pack2(e0, e0);
            *(unsigned long long*)(psw + (lane + 32) * 8 + gj * 2) = pack2(e1, e1);
        }
        __syncwarp();

        // --- PV: lanes over d (4 per lane); p read pre-duplicated -> no packs ---
        #pragma unroll 8
        for (int u = 0; u < BSn; ++u) {
            ulonglong2 pa = *(const ulonglong2*)(psw + u * 8);       // {p0,p0},{p1,p1}
            ulonglong2 pb = *(const ulonglong2*)(psw + u * 8 + 4);   // {p2,p2},{p3,p3}
            ulonglong2 vv = *(const ulonglong2*)(vs + u * KROW + lane * 4);
            FMA2(o[0][0], pa.x, vv.x); FMA2(o[0][1], pa.x, vv.y);
            FMA2(o[1][0], pa.y, vv.x); FMA2(o[1][1], pa.y, vv.y);
            FMA2(o[2][0], pb.x, vv.x); FMA2(o[2][1], pb.x, vv.y);
            FMA2(o[3][0], pb.y, vv.x); FMA2(o[3][1], pb.y, vv.y);
        }
    }

    // --- write O: out[l, h*G + g, 4*lane .. +3] ---
    float* op = out + (size_t)(l * HQn + h * Gn) * Dn;
    #pragma unroll
    for (int gj = 0; gj < 4; ++gj) {
        float f0, f1, f2, f3;
        unpack2(o[gj][0], f0, f1);
        unpack2(o[gj][1], f2, f3);
        float4 r = make_float4(f0, f1, f2, f3);
        *(float4*)(op + (g0 + gj) * Dn + lane * 4) = r;
    }
}

extern "C" void kernel_launch(void* const* d_in, const int* in_sizes, int n_in,
                              void* d_out, int out_size) {
    const float* q  = (const float*)d_in[0];
    const float* k  = (const float*)d_in[1];
    const float* v  = (const float*)d_in[2];
    const float* w  = (const float*)d_in[3];
    const int*   bi = (const int*)d_in[4];
    float* out = (float*)d_out;

    cudaFuncSetAttribute(hsa_prefill_kernel,
                         cudaFuncAttributeMaxDynamicSharedMemorySize, SMEM_BYTES);
    dim3 grid(Hn, LQ);   // 2 x 256 = 512 CTAs
    hsa_prefill_kernel<<<grid, 128, SMEM_BYTES>>>(q, k, v, w, bi, out);
}

// round 5
// speedup vs baseline: 1.1061x; 1.1009x over previous
#include <cuda_runtime.h>
#include <cuda.h>
#include <cstdint>

// ---------------------------------------------------------------------------
// Block-sparse attention prefill (HSA), TMA-pipelined.
// Per (l, h): for each of S=16 selected 64x128 KV blocks:
//   scores = q . K_blk * sm_scale ; p = softmax_64(scores) * w * valid
//   o += p . V_blk
// B=1, Lq=256, Lkv=4096, HQ=32, H=2, D=128, S=16, BS=64, G=16.
// K double-buffered + V single-buffered via TMA (SW128) with mbarriers.
// ---------------------------------------------------------------------------

#define FMA2(acc, a, b) asm("fma.rn.f32x2 %0, %1, %2, %0;" : "+l"(acc) : "l"(a), "l"(b))

__device__ __forceinline__ void unpack2(unsigned long long v, float& lo, float& hi) {
    asm("mov.b64 {%0, %1}, %2;" : "=f"(lo), "=f"(hi) : "l"(v));
}
__device__ __forceinline__ uint32_t su32(const void* p) {
    return (uint32_t)__cvta_generic_to_shared(p);
}

#define MBAR_INIT(a, c) \
    asm volatile("mbarrier.init.shared.b64 [%0], %1;" :: "r"(a), "r"(c) : "memory")
#define MBAR_EXPECT(a, b) \
    asm volatile("mbarrier.arrive.expect_tx.shared.b64 _, [%0], %1;" :: "r"(a), "r"(b) : "memory")
#define TMA3D(smem, map, x, y, z, mbar) \
    asm volatile("cp.async.bulk.tensor.3d.shared::cta.global.tile.mbarrier::complete_tx::bytes " \
                 "[%0], [%1, {%2, %3, %4}], [%5];" \
                 :: "r"(smem), "l"(map), "r"(x), "r"(y), "r"(z), "r"(mbar) : "memory")

__device__ __forceinline__ void mbar_wait(uint32_t mbar, uint32_t parity) {
    asm volatile(
        "{\n\t.reg .pred P;\n"
        "LW_%=:\n\t"
        "mbarrier.try_wait.parity.acquire.cta.shared::cta.b64 P, [%0], %1, 0x989680;\n\t"
        "@P bra LD_%=;\n\t"
        "bra LW_%=;\n"
        "LD_%=:\n\t}" :: "r"(mbar), "r"(parity) : "memory");
}

namespace hsa {
constexpr int LQ = 256, HQn = 32, Hn = 2, Dn = 128, Sn = 16, BSn = 64, Gn = 16;
constexpr float SM_SCALE = 0.08838834764831845f;  // 1/sqrt(128)

constexpr int TILE_B = 32768;            // 64 rows x 512B = 4 SW128 panels of 8KB
constexpr int KB0    = 0;
constexpr int KB1    = 32768;
constexpr int VB     = 65536;
constexpr int QS_OFF = 98304;            // 2048 f32 (16 heads x 128, pre-scaled)
constexpr int PS_OFF = 106496;           // 4 warps x 64 x 8 f32 (p duplicated {p,p})
constexpr int WS_OFF = 114688;           // 256 f32
constexpr int BI_OFF = 115712;           // 16 int
constexpr int MB_OFF = 115776;           // 3 mbarriers (8B each)
constexpr int SMEM_BYTES = 115840;       // x2 CTAs = 231680 <= 228KB/SM
}  // namespace hsa
using namespace hsa;

template <bool USE_TMA>
__global__ __launch_bounds__(128, 2)
void hsa_prefill(const __grid_constant__ CUtensorMap tmk,
                 const __grid_constant__ CUtensorMap tmv,
                 const float* __restrict__ q, const float* __restrict__ k,
                 const float* __restrict__ v, const float* __restrict__ w,
                 const int* __restrict__ bi, float* __restrict__ out)
{
    extern __shared__ char sm[];
    float* qs  = (float*)(sm + QS_OFF);
    float* ps  = (float*)(sm + PS_OFF);
    float* wsm = (float*)(sm + WS_OFF);
    int*   bis = (int*)(sm + BI_OFF);
    const uint32_t mb = su32(sm + MB_OFF);   // +0: kbar0, +8: kbar1, +16: vbar

    const int h    = blockIdx.x;
    const int l    = blockIdx.y;
    const int tid  = threadIdx.x;
    const int warp = tid >> 5;
    const int lane = tid & 31;

    if (USE_TMA && tid == 0) {
        MBAR_INIT(mb + 0, 1);
        MBAR_INIT(mb + 8, 1);
        MBAR_INIT(mb + 16, 1);
    }

    // --- Stage q (pre-scaled), w, block indices ---
    {
        const float4* qg = (const float4*)(q + (size_t)(l * HQn + h * Gn) * Dn);
        float4* qs4 = (float4*)qs;
        #pragma unroll
        for (int j = 0; j < 4; ++j) {
            int i = tid + j * 128;
            float4 t = qg[i];
            t.x *= SM_SCALE; t.y *= SM_SCALE; t.z *= SM_SCALE; t.w *= SM_SCALE;
            qs4[i] = t;
        }
        if (tid < 64)
            ((float4*)wsm)[tid] =
                ((const float4*)(w + (size_t)(l * HQn + h * Gn) * Sn))[tid];
        if (tid < 16)
            bis[tid] = bi[(l * Hn + h) * Sn + tid];
    }
    __syncthreads();

    // --- Prologue: launch K_0 (TMA path) ---
    if (USE_TMA && tid == 0) {
        int b0 = max(bis[0], 0) * BSn;
        MBAR_EXPECT(mb + 0, TILE_B);
        #pragma unroll
        for (int p = 0; p < 4; ++p)
            TMA3D(su32(sm + KB0 + p * 8192), &tmk, 32 * p, h, b0, mb + 0);
    }

    const int g0  = warp * 4;                // 4 query heads per warp
    const int lx8 = (lane & 7) << 4;         // SW128 per-lane xor component (bytes)
    float* psw = ps + warp * 512;

    unsigned long long o[4][2];
    #pragma unroll
    for (int a = 0; a < 4; ++a) { o[a][0] = 0ull; o[a][1] = 0ull; }

    uint32_t kph0 = 0, kph1 = 0, vph = 0;
    // fallback gather base pointers (f4 units; row stride Hn*Dn/4 = 64)
    const float4* kb4 = (const float4*)(k + h * Dn);
    const float4* vb4 = (const float4*)(v + h * Dn);

    for (int s = 0; s < Sn; ++s) {
        const int blkraw = bis[s];
        const int blkc   = max(blkraw, 0);

        __syncthreads();   // prev iter's smem readers done (V buf + other K buf free)

        const char* kt;
        if (USE_TMA) {
            if (tid == 0) {
                MBAR_EXPECT(mb + 16, TILE_B);
                #pragma unroll
                for (int p = 0; p < 4; ++p)
                    TMA3D(su32(sm + VB + p * 8192), &tmv, 32 * p, h, blkc * BSn, mb + 16);
                if (s + 1 < Sn) {
                    int bn = max(bis[s + 1], 0) * BSn;
                    uint32_t kbar = mb + 8u * ((s + 1) & 1);
                    char* kdst = sm + (((s + 1) & 1) ? KB1 : KB0);
                    MBAR_EXPECT(kbar, TILE_B);
                    #pragma unroll
                    for (int p = 0; p < 4; ++p)
                        TMA3D(su32(kdst + p * 8192), &tmk, 32 * p, h, bn, kbar);
                }
            }
            // wait K_s (issued one full iteration ago)
            if (s & 1) { mbar_wait(mb + 8, kph1); kph1 ^= 1; }
            else       { mbar_wait(mb + 0, kph0); kph0 ^= 1; }
            kt = sm + ((s & 1) ? KB1 : KB0);
        } else {
            // fallback: cooperative LDG -> swizzled STS for K and V
            const float4* krow = kb4 + (size_t)blkc * BSn * 64;
            const float4* vrow = vb4 + (size_t)blkc * BSn * 64;
            #pragma unroll
            for (int j = 0; j < 16; ++j) {
                int c = tid + j * 128;
                int u = c >> 5, d4 = c & 31;
                int panel = d4 >> 3, chunk = d4 & 7;
                int so = panel * 8192 + u * 128 + ((chunk ^ (u & 7)) << 4);
                *(float4*)(sm + KB0 + so) = krow[u * 64 + d4];
                *(float4*)(sm + VB  + so) = vrow[u * 64 + d4];
            }
            __syncthreads();
            kt = sm + KB0;
        }

        // --- QK: lanes over keys (u = lane, lane+32), f32x2 over d pairs ---
        unsigned long long acc[4][2];
        #pragma unroll
        for (int a = 0; a < 4; ++a) { acc[a][0] = 0ull; acc[a][1] = 0ull; }

        #pragma unroll
        for (int p4 = 0; p4 < 4; ++p4) {
            const char* kp0 = kt + p4 * 8192 + lane * 128;
            const char* kp1 = kp0 + 4096;    // +32 rows; (lane+32)&7 == lane&7
            #pragma unroll
            for (int cc = 0; cc < 8; ++cc) {
                int co = (cc << 4) ^ lx8;    // SW128 de-swizzle
                ulonglong2 ka = *(const ulonglong2*)(kp0 + co);
                ulonglong2 kc = *(const ulonglong2*)(kp1 + co);
                const float* qd = qs + p4 * 32 + cc * 4;
                #pragma unroll
                for (int gj = 0; gj < 4; ++gj) {
                    ulonglong2 qv = *(const ulonglong2*)(qd + (g0 + gj) * Dn);
                    FMA2(acc[gj][0], qv.x, ka.x);
                    FMA2(acc[gj][0], qv.y, ka.y);
                    FMA2(acc[gj][1], qv.x, kc.x);
                    FMA2(acc[gj][1], qv.y, kc.y);
                }
            }
        }

        // --- per-block softmax over 64 keys + weight; p stored duplicated {p,p} ---
        float r0[4], r1[4];
        #pragma unroll
        for (int gj = 0; gj < 4; ++gj) {
            float a0, a1, b0, b1;
            unpack2(acc[gj][0], a0, a1);
            unpack2(acc[gj][1], b0, b1);
            float s0 = a0 + a1;
            float s1 = b0 + b1;
            float m = fmaxf(s0, s1);
            #pragma unroll
            for (int off = 16; off > 0; off >>= 1)
                m = fmaxf(m, __shfl_xor_sync(0xffffffffu, m, off));
            float e0 = __expf(s0 - m);
            float e1 = __expf(s1 - m);
            float sum = e0 + e1;
            #pragma unroll
            for (int off = 16; off > 0; off >>= 1)
                sum += __shfl_xor_sync(0xffffffffu, sum, off);
            float wv = (blkraw >= 0) ? wsm[(g0 + gj) * Sn + s] : 0.0f;
            float coef = __fdividef(wv, sum);
            r0[gj] = e0 * coef;
            r1[gj] = e1 * coef;
        }
        *(float4*)(psw + lane * 8)            = make_float4(r0[0], r0[0], r0[1], r0[1]);
        *(float4*)(psw + lane * 8 + 4)        = make_float4(r0[2], r0[2], r0[3], r0[3]);
        *(float4*)(psw + (lane + 32) * 8)     = make_float4(r1[0], r1[0], r1[1], r1[1]);
        *(float4*)(psw + (lane + 32) * 8 + 4) = make_float4(r1[2], r1[2], r1[3], r1[3]);
        __syncwarp();

        // --- wait V_s (TMA issued at iter top; hidden behind QK+softmax) ---
        if (USE_TMA) { mbar_wait(mb + 16, vph); vph ^= 1; }

        // --- PV: lanes over d-chunks; p read pre-duplicated -> zero pack ops ---
        const char* vt = sm + VB + (lane >> 3) * 8192;   // lane's 32-float d-panel
        #pragma unroll 8
        for (int u = 0; u < BSn; ++u) {
            ulonglong2 pa = *(const ulonglong2*)(psw + u * 8);      // {p0,p0},{p1,p1}
            ulonglong2 pb = *(const ulonglong2*)(psw + u * 8 + 4);  // {p2,p2},{p3,p3}
            ulonglong2 vv = *(const ulonglong2*)(vt + u * 128 + (lx8 ^ ((u & 7) << 4)));
            FMA2(o[0][0], pa.x, vv.x); FMA2(o[0][1], pa.x, vv.y);
            FMA2(o[1][0], pa.y, vv.x); FMA2(o[1][1], pa.y, vv.y);
            FMA2(o[2][0], pb.x, vv.x); FMA2(o[2][1], pb.x, vv.y);
            FMA2(o[3][0], pb.y, vv.x); FMA2(o[3][1], pb.y, vv.y);
        }
    }

    // --- write O: lane covers d = (lane>>3)*32 + (lane&7)*4 .. +3 ---
    const int dbase = ((lane >> 3) << 5) + ((lane & 7) << 2);
    float* op = out + (size_t)(l * HQn + h * Gn) * Dn;
    #pragma unroll
    for (int gj = 0; gj < 4; ++gj) {
        float f0, f1, f2, f3;
        unpack2(o[gj][0], f0, f1);
        unpack2(o[gj][1], f2, f3);
        *(float4*)(op + (g0 + gj) * Dn + dbase) = make_float4(f0, f1, f2, f3);
    }
}

// ---------------------------------------------------------------------------
// Host
// ---------------------------------------------------------------------------

typedef CUresult (*EncodeTiled_t)(
    CUtensorMap*, CUtensorMapDataType, cuuint32_t, void*,
    const cuuint64_t*, const cuuint64_t*, const cuuint32_t*, const cuuint32_t*,
    CUtensorMapInterleave, CUtensorMapSwizzle, CUtensorMapL2promotion,
    CUtensorMapFloatOOBfill);

static EncodeTiled_t get_encode_fn() {
    void* fn = nullptr;
    cudaDriverEntryPointQueryResult qr = cudaDriverEntryPointSymbolNotFound;
#if CUDART_VERSION >= 12050
    if (cudaGetDriverEntryPointByVersion("cuTensorMapEncodeTiled", &fn, 12000,
                                         cudaEnableDefault, &qr) != cudaSuccess ||
        qr != cudaDriverEntryPointSuccess)
        fn = nullptr;
#else
    if (cudaGetDriverEntryPoint("cuTensorMapEncodeTiled", &fn,
                                cudaEnableDefault, &qr) != cudaSuccess ||
        qr != cudaDriverEntryPointSuccess)
        fn = nullptr;
#endif
    return (EncodeTiled_t)fn;
}

static bool make_map(EncodeTiled_t enc, CUtensorMap* tm, const void* base) {
    // global tensor: f32 [Lkv=4096][H=2][D=128], innermost D contiguous
    cuuint64_t dims[3]    = {128, 2, 4096};
    cuuint64_t strides[2] = {128ull * 4ull, 256ull * 4ull};  // bytes for dims 1,2
    cuuint32_t box[3]     = {32, 1, 64};                     // 128B panel x 64 keys
    cuuint32_t estr[3]    = {1, 1, 1};
    CUresult r = enc(tm, CU_TENSOR_MAP_DATA_TYPE_FLOAT32, 3, (void*)base,
                     dims, strides, box, estr,
                     CU_TENSOR_MAP_INTERLEAVE_NONE, CU_TENSOR_MAP_SWIZZLE_128B,
                     CU_TENSOR_MAP_L2_PROMOTION_L2_128B,
                     CU_TENSOR_MAP_FLOAT_OOB_FILL_NONE);
    return r == CUDA_SUCCESS;
}

extern "C" void kernel_launch(void* const* d_in, const int* in_sizes, int n_in,
                              void* d_out, int out_size) {
    const float* q  = (const float*)d_in[0];
    const float* k  = (const float*)d_in[1];
    const float* v  = (const float*)d_in[2];
    const float* w  = (const float*)d_in[3];
    const int*   bi = (const int*)d_in[4];
    float* out = (float*)d_out;

    CUtensorMap tmk, tmv;
    __builtin_memset(&tmk, 0, sizeof(tmk));
    __builtin_memset(&tmv, 0, sizeof(tmv));

    EncodeTiled_t enc = get_encode_fn();
    bool tma_ok = enc && make_map(enc, &tmk, k) && make_map(enc, &tmv, v);

    dim3 grid(Hn, LQ);
    if (tma_ok) {
        cudaFuncSetAttribute(hsa_prefill<true>,
                             cudaFuncAttributeMaxDynamicSharedMemorySize, SMEM_BYTES);
        hsa_prefill<true><<<grid, 128, SMEM_BYTES>>>(tmk, tmv, q, k, v, w, bi, out);
    } else {
        cudaFuncSetAttribute(hsa_prefill<false>,
                             cudaFuncAttributeMaxDynamicSharedMemorySize, SMEM_BYTES);
        hsa_prefill<false><<<grid, 128, SMEM_BYTES>>>(tmk, tmv, q, k, v, w, bi, out);
    }
}